// round 1
// baseline (speedup 1.0000x reference)
#include <cuda_runtime.h>
#include <math.h>

// Problem constants
#define T_STEPS 200
#define BATCH   1024
#define XD      48
#define AD      15
#define IN_DIM  64      // XD + AD + 1
#define H_DIM   512
#define G4      2048    // 4*H
#define KTOT    576     // IN_DIM + H_DIM
#define OUT_DIM 32
#define H1      513     // H + 1

// Scratch (static device allocations only; no cudaMalloc anywhere)
__device__ float g_h[2][BATCH * H_DIM];   // double-buffered hidden state
__device__ float g_c[BATCH * H_DIM];      // cell state (tile-private, single buffer)
__device__ float g_z1[2][BATCH * H1];     // hidden of the two MLP heads
__device__ float g_maxm;

// ---------------------------------------------------------------------------
// Init: zero h[0] and c
// ---------------------------------------------------------------------------
__global__ __launch_bounds__(256) void zero_kernel() {
    int idx = blockIdx.x * blockDim.x + threadIdx.x;
    int stride = gridDim.x * blockDim.x;
    for (int i = idx; i < BATCH * H_DIM; i += stride) {
        g_h[0][i] = 0.0f;
        g_c[i]    = 0.0f;
    }
}

// ---------------------------------------------------------------------------
// max(m) over T*B elements — single CTA
// ---------------------------------------------------------------------------
__global__ __launch_bounds__(256) void maxm_kernel(const float* __restrict__ m) {
    __shared__ float red[256];
    float v = -1e30f;
    for (int i = threadIdx.x; i < T_STEPS * BATCH; i += 256)
        v = fmaxf(v, m[i]);
    red[threadIdx.x] = v;
    __syncthreads();
    for (int s = 128; s > 0; s >>= 1) {
        if (threadIdx.x < s) red[threadIdx.x] = fmaxf(red[threadIdx.x], red[threadIdx.x + s]);
        __syncthreads();
    }
    if (threadIdx.x == 0) g_maxm = red[0];
}

// ---------------------------------------------------------------------------
// Fused LSTM step: gates = x_in @ w_ih^T + h @ w_hh^T + (b_ih + b_hh),
// then cell update. CTA tile: 64 batch rows x 32 h-cols x all 4 gates
// (n_local = gate*32 + hc, 128 gate columns). One barrier-free fusion:
// i/f/g/o for a given (b,hc) live in the same thread's registers.
// ---------------------------------------------------------------------------
#define KC  32
#define SIS 65    // sIn row stride (conflict-free)
#define SWS 129   // sW row stride (conflict-free)

__global__ __launch_bounds__(256) void step_kernel(
    const float* __restrict__ x, const float* __restrict__ a,
    const float* __restrict__ w_ih, const float* __restrict__ w_hh,
    const float* __restrict__ b_ih, const float* __restrict__ b_hh,
    int s)
{
    __shared__ float sIn[KC * SIS];   // [k][b]  64 batch
    __shared__ float sW[KC * SWS];    // [k][n]  128 gate cols

    const int hT = blockIdx.x;            // 0..15  (32 h-cols each)
    const int bT = blockIdx.y;            // 0..15  (64 batch rows each)
    const int b0 = bT * 64;
    const int h0 = hT * 32;
    const int tid = threadIdx.x;
    const int tx = tid & 15;              // -> gate cols tx + 16*j
    const int ty = tid >> 4;              // -> batch rows ty + 16*i

    const float* __restrict__ hbuf = g_h[s & 1];
    float* __restrict__ hout       = g_h[(s + 1) & 1];
    const int trow = T_STEPS - 1 - s;     // flipped sequence index
    const float tval = (float)s / g_maxm;

    // Biases for this thread's 8 gate columns: n = gate*512 + h0 + tx + 16*m, j = 2*gate + m
    float bsum[8];
#pragma unroll
    for (int j = 0; j < 8; j++) {
        int n = (j >> 1) * H_DIM + h0 + tx + 16 * (j & 1);
        bsum[j] = b_ih[n] + b_hh[n];
    }

    float acc[4][8];
#pragma unroll
    for (int i = 0; i < 4; i++)
#pragma unroll
        for (int j = 0; j < 8; j++) acc[i][j] = 0.0f;

    for (int k0 = 0; k0 < KTOT; k0 += KC) {
        // Stage input tile [KC x 64]: warp lanes sweep kk (coalesced, conflict-free)
#pragma unroll
        for (int i = 0; i < 8; i++) {
            int lin = tid + i * 256;
            int kk = lin & 31, bb = lin >> 5;
            int kG = k0 + kk;
            int b = b0 + bb;
            float v;
            if (kG >= IN_DIM)           v = hbuf[b * H_DIM + (kG - IN_DIM)];
            else if (kG < XD)           v = x[(size_t)trow * BATCH * XD + b * XD + kG];
            else if (kG < XD + AD)      v = a[(size_t)trow * BATCH * AD + b * AD + (kG - XD)];
            else                        v = tval;
            sIn[kk * SIS + bb] = v;
        }
        // Stage weight tile [KC x 128]
#pragma unroll
        for (int i = 0; i < 16; i++) {
            int lin = tid + i * 256;
            int kk = lin & 31, nn = lin >> 5;
            int gate = nn >> 5, hc = nn & 31;
            int row = gate * H_DIM + h0 + hc;
            int kG = k0 + kk;
            float w = (kG < IN_DIM) ? w_ih[row * IN_DIM + kG]
                                    : w_hh[row * H_DIM + (kG - IN_DIM)];
            sW[kk * SWS + nn] = w;
        }
        __syncthreads();

#pragma unroll
        for (int k = 0; k < KC; k++) {
            float rIn[4], rW[8];
#pragma unroll
            for (int i = 0; i < 4; i++) rIn[i] = sIn[k * SIS + ty + 16 * i];
#pragma unroll
            for (int j = 0; j < 8; j++) rW[j] = sW[k * SWS + tx + 16 * j];
#pragma unroll
            for (int i = 0; i < 4; i++)
#pragma unroll
                for (int j = 0; j < 8; j++)
                    acc[i][j] += rIn[i] * rW[j];
        }
        __syncthreads();
    }

    // LSTM cell update — this thread owns gates (i,f,g,o) for rows b0+ty+16i,
    // h-cols h0+tx+16m:  gate index j = 2*gate + m.
#pragma unroll
    for (int i = 0; i < 4; i++) {
        int b = b0 + ty + 16 * i;
#pragma unroll
        for (int mm = 0; mm < 2; mm++) {
            int hc = h0 + tx + 16 * mm;
            float iv = acc[i][0 + mm] + bsum[0 + mm];
            float fv = acc[i][2 + mm] + bsum[2 + mm];
            float gv = acc[i][4 + mm] + bsum[4 + mm];
            float ov = acc[i][6 + mm] + bsum[6 + mm];
            iv = 1.0f / (1.0f + expf(-iv));
            fv = 1.0f / (1.0f + expf(-fv));
            ov = 1.0f / (1.0f + expf(-ov));
            gv = tanhf(gv);
            int idx = b * H_DIM + hc;
            float c = fv * g_c[idx] + iv * gv;
            g_c[idx] = c;
            hout[idx] = ov * tanhf(c);
        }
    }
}

// ---------------------------------------------------------------------------
// MLP layer 1: z1 = tanh(h_final @ w1^T + b1), two heads. M=1024, N=513, K=512.
// 64x64 tile, thread 4x4 microtile.
// ---------------------------------------------------------------------------
__global__ __launch_bounds__(256) void mlp1_kernel(
    const float* __restrict__ lw1, const float* __restrict__ lb1,
    const float* __restrict__ vw1, const float* __restrict__ vb1)
{
    __shared__ float sA[KC * SIS];       // [k][b]  64
    __shared__ float sW[KC * SIS];       // [k][n]  64 (same stride works)

    const int head = blockIdx.z;
    const float* __restrict__ w  = head ? vw1 : lw1;
    const float* __restrict__ b1 = head ? vb1 : lb1;
    const float* __restrict__ A  = g_h[0];        // s=199 wrote buffer 0
    float* __restrict__ z1 = g_z1[head];

    const int n0 = blockIdx.x * 64;
    const int b0 = blockIdx.y * 64;
    const int tid = threadIdx.x;
    const int tx = tid & 15, ty = tid >> 4;

    float acc[4][4];
#pragma unroll
    for (int i = 0; i < 4; i++)
#pragma unroll
        for (int j = 0; j < 4; j++) acc[i][j] = 0.0f;

    for (int k0 = 0; k0 < H_DIM; k0 += KC) {
#pragma unroll
        for (int i = 0; i < 8; i++) {
            int lin = tid + i * 256;
            int kk = lin & 31, bb = lin >> 5;
            sA[kk * SIS + bb] = A[(b0 + bb) * H_DIM + k0 + kk];
        }
#pragma unroll
        for (int i = 0; i < 8; i++) {
            int lin = tid + i * 256;
            int kk = lin & 31, nn = lin >> 5;
            int n = n0 + nn;
            sW[kk * SIS + nn] = (n < H1) ? w[n * H_DIM + k0 + kk] : 0.0f;
        }
        __syncthreads();
#pragma unroll
        for (int k = 0; k < KC; k++) {
            float rA[4], rW[4];
#pragma unroll
            for (int i = 0; i < 4; i++) rA[i] = sA[k * SIS + ty + 16 * i];
#pragma unroll
            for (int j = 0; j < 4; j++) rW[j] = sW[k * SIS + tx + 16 * j];
#pragma unroll
            for (int i = 0; i < 4; i++)
#pragma unroll
                for (int j = 0; j < 4; j++)
                    acc[i][j] += rA[i] * rW[j];
        }
        __syncthreads();
    }

#pragma unroll
    for (int j = 0; j < 4; j++) {
        int n = n0 + tx + 16 * j;
        if (n < H1) {
            float bv = b1[n];
#pragma unroll
            for (int i = 0; i < 4; i++) {
                int b = b0 + ty + 16 * i;
                z1[b * H1 + n] = tanhf(acc[i][j] + bv);
            }
        }
    }
}

// ---------------------------------------------------------------------------
// MLP layer 2: out = tanh(z1 @ w2^T + b2), two heads. M=1024, N=32, K=513.
// Block: 32 batch rows; thread = (o, row-group), smem-staged operands.
// ---------------------------------------------------------------------------
__global__ __launch_bounds__(256) void mlp2_kernel(
    const float* __restrict__ lw2, const float* __restrict__ lb2,
    const float* __restrict__ vw2, const float* __restrict__ vb2,
    float* __restrict__ out)
{
    __shared__ float z1s[32 * 65];  // [row][kk]
    __shared__ float w2s[32 * 65];  // [o][kk]

    const int head = blockIdx.y;
    const float* __restrict__ w2 = head ? vw2 : lw2;
    const float* __restrict__ b2 = head ? vb2 : lb2;
    const float* __restrict__ z1 = g_z1[head];

    const int r0 = blockIdx.x * 32;
    const int tid = threadIdx.x;
    const int o  = tid & 31;
    const int rg = tid >> 5;        // 0..7 -> rows rg*4 .. rg*4+3

    float acc[4] = {0.f, 0.f, 0.f, 0.f};

    for (int k0 = 0; k0 < H1; k0 += 64) {
#pragma unroll
        for (int i = 0; i < 8; i++) {
            int lin = tid + i * 256;
            int kk = lin & 63, rr = lin >> 6;
            int k = k0 + kk;
            z1s[rr * 65 + kk] = (k < H1) ? z1[(r0 + rr) * H1 + k] : 0.0f;
            w2s[rr * 65 + kk] = (k < H1) ? w2[rr * H1 + k] : 0.0f;   // rr == o row
        }
        __syncthreads();
#pragma unroll
        for (int kk = 0; kk < 64; kk++) {
            float wv = w2s[o * 65 + kk];
#pragma unroll
            for (int r = 0; r < 4; r++)
                acc[r] += z1s[(rg * 4 + r) * 65 + kk] * wv;
        }
        __syncthreads();
    }

    float bv = b2[o];
#pragma unroll
    for (int r = 0; r < 4; r++) {
        int b = r0 + rg * 4 + r;
        out[(size_t)head * BATCH * OUT_DIM + b * OUT_DIM + o] = tanhf(acc[r] + bv);
    }
}

// ---------------------------------------------------------------------------
// Launch
// ---------------------------------------------------------------------------
extern "C" void kernel_launch(void* const* d_in, const int* in_sizes, int n_in,
                              void* d_out, int out_size) {
    const float* x    = (const float*)d_in[0];
    const float* a    = (const float*)d_in[1];
    const float* m    = (const float*)d_in[2];
    const float* w_ih = (const float*)d_in[3];
    const float* w_hh = (const float*)d_in[4];
    const float* b_ih = (const float*)d_in[5];
    const float* b_hh = (const float*)d_in[6];
    const float* lw1  = (const float*)d_in[7];
    const float* lb1  = (const float*)d_in[8];
    const float* lw2  = (const float*)d_in[9];
    const float* lb2  = (const float*)d_in[10];
    const float* vw1  = (const float*)d_in[11];
    const float* vb1  = (const float*)d_in[12];
    const float* vw2  = (const float*)d_in[13];
    const float* vb2  = (const float*)d_in[14];

    zero_kernel<<<512, 256>>>();
    maxm_kernel<<<1, 256>>>(m);

    for (int s = 0; s < T_STEPS; s++)
        step_kernel<<<dim3(16, 16), 256>>>(x, a, w_ih, w_hh, b_ih, b_hh, s);

    mlp1_kernel<<<dim3(9, 16, 2), 256>>>(lw1, lb1, vw1, vb1);
    mlp2_kernel<<<dim3(32, 2), 256>>>(lw2, lb2, vw2, vb2, (float*)d_out);
}

// round 2
// speedup vs baseline: 1.0002x; 1.0002x over previous
#include <cuda_runtime.h>
#include <math.h>

// Problem constants
#define T_STEPS 200
#define BATCH   1024
#define XD      48
#define AD      15
#define IN_DIM  64      // XD + AD + 1
#define H_DIM   512
#define G4      2048    // 4*H
#define KTOT    576     // IN_DIM + H_DIM
#define OUT_DIM 32
#define H1      513     // H + 1

// Scratch (static device allocations only; no cudaMalloc anywhere)
__device__ float g_h[2][BATCH * H_DIM];   // double-buffered hidden state
__device__ float g_c[BATCH * H_DIM];      // cell state (tile-private, single buffer)
__device__ float g_z1[2][BATCH * H1];     // hidden of the two MLP heads
__device__ float g_maxm;

// ---------------------------------------------------------------------------
// Init: zero h[0] and c
// ---------------------------------------------------------------------------
__global__ __launch_bounds__(256) void zero_kernel() {
    int idx = blockIdx.x * blockDim.x + threadIdx.x;
    int stride = gridDim.x * blockDim.x;
    for (int i = idx; i < BATCH * H_DIM; i += stride) {
        g_h[0][i] = 0.0f;
        g_c[i]    = 0.0f;
    }
}

// ---------------------------------------------------------------------------
// max(m) over T*B elements — single CTA
// ---------------------------------------------------------------------------
__global__ __launch_bounds__(256) void maxm_kernel(const float* __restrict__ m) {
    __shared__ float red[256];
    float v = -1e30f;
    for (int i = threadIdx.x; i < T_STEPS * BATCH; i += 256)
        v = fmaxf(v, m[i]);
    red[threadIdx.x] = v;
    __syncthreads();
    for (int s = 128; s > 0; s >>= 1) {
        if (threadIdx.x < s) red[threadIdx.x] = fmaxf(red[threadIdx.x], red[threadIdx.x + s]);
        __syncthreads();
    }
    if (threadIdx.x == 0) g_maxm = red[0];
}

// ---------------------------------------------------------------------------
// Fused LSTM step: gates = x_in @ w_ih^T + h @ w_hh^T + (b_ih + b_hh),
// then cell update. CTA tile: 64 batch rows x 32 h-cols x all 4 gates
// (n_local = gate*32 + hc, 128 gate columns). One barrier-free fusion:
// i/f/g/o for a given (b,hc) live in the same thread's registers.
// ---------------------------------------------------------------------------
#define KC  32
#define SIS 65    // sIn row stride (conflict-free)
#define SWS 129   // sW row stride (conflict-free)

__global__ __launch_bounds__(256) void step_kernel(
    const float* __restrict__ x, const float* __restrict__ a,
    const float* __restrict__ w_ih, const float* __restrict__ w_hh,
    const float* __restrict__ b_ih, const float* __restrict__ b_hh,
    int s)
{
    __shared__ float sIn[KC * SIS];   // [k][b]  64 batch
    __shared__ float sW[KC * SWS];    // [k][n]  128 gate cols

    const int hT = blockIdx.x;            // 0..15  (32 h-cols each)
    const int bT = blockIdx.y;            // 0..15  (64 batch rows each)
    const int b0 = bT * 64;
    const int h0 = hT * 32;
    const int tid = threadIdx.x;
    const int tx = tid & 15;              // -> gate cols tx + 16*j
    const int ty = tid >> 4;              // -> batch rows ty + 16*i

    const float* __restrict__ hbuf = g_h[s & 1];
    float* __restrict__ hout       = g_h[(s + 1) & 1];
    const int trow = T_STEPS - 1 - s;     // flipped sequence index
    const float tval = (float)s / g_maxm;

    // Biases for this thread's 8 gate columns: n = gate*512 + h0 + tx + 16*m, j = 2*gate + m
    float bsum[8];
#pragma unroll
    for (int j = 0; j < 8; j++) {
        int n = (j >> 1) * H_DIM + h0 + tx + 16 * (j & 1);
        bsum[j] = b_ih[n] + b_hh[n];
    }

    float acc[4][8];
#pragma unroll
    for (int i = 0; i < 4; i++)
#pragma unroll
        for (int j = 0; j < 8; j++) acc[i][j] = 0.0f;

    for (int k0 = 0; k0 < KTOT; k0 += KC) {
        // Stage input tile [KC x 64]: warp lanes sweep kk (coalesced, conflict-free)
#pragma unroll
        for (int i = 0; i < 8; i++) {
            int lin = tid + i * 256;
            int kk = lin & 31, bb = lin >> 5;
            int kG = k0 + kk;
            int b = b0 + bb;
            float v;
            if (kG >= IN_DIM)           v = hbuf[b * H_DIM + (kG - IN_DIM)];
            else if (kG < XD)           v = x[(size_t)trow * BATCH * XD + b * XD + kG];
            else if (kG < XD + AD)      v = a[(size_t)trow * BATCH * AD + b * AD + (kG - XD)];
            else                        v = tval;
            sIn[kk * SIS + bb] = v;
        }
        // Stage weight tile [KC x 128]
#pragma unroll
        for (int i = 0; i < 16; i++) {
            int lin = tid + i * 256;
            int kk = lin & 31, nn = lin >> 5;
            int gate = nn >> 5, hc = nn & 31;
            int row = gate * H_DIM + h0 + hc;
            int kG = k0 + kk;
            float w = (kG < IN_DIM) ? w_ih[row * IN_DIM + kG]
                                    : w_hh[row * H_DIM + (kG - IN_DIM)];
            sW[kk * SWS + nn] = w;
        }
        __syncthreads();

#pragma unroll
        for (int k = 0; k < KC; k++) {
            float rIn[4], rW[8];
#pragma unroll
            for (int i = 0; i < 4; i++) rIn[i] = sIn[k * SIS + ty + 16 * i];
#pragma unroll
            for (int j = 0; j < 8; j++) rW[j] = sW[k * SWS + tx + 16 * j];
#pragma unroll
            for (int i = 0; i < 4; i++)
#pragma unroll
                for (int j = 0; j < 8; j++)
                    acc[i][j] += rIn[i] * rW[j];
        }
        __syncthreads();
    }

    // LSTM cell update — this thread owns gates (i,f,g,o) for rows b0+ty+16i,
    // h-cols h0+tx+16m:  gate index j = 2*gate + m.
#pragma unroll
    for (int i = 0; i < 4; i++) {
        int b = b0 + ty + 16 * i;
#pragma unroll
        for (int mm = 0; mm < 2; mm++) {
            int hc = h0 + tx + 16 * mm;
            float iv = acc[i][0 + mm] + bsum[0 + mm];
            float fv = acc[i][2 + mm] + bsum[2 + mm];
            float gv = acc[i][4 + mm] + bsum[4 + mm];
            float ov = acc[i][6 + mm] + bsum[6 + mm];
            iv = 1.0f / (1.0f + expf(-iv));
            fv = 1.0f / (1.0f + expf(-fv));
            ov = 1.0f / (1.0f + expf(-ov));
            gv = tanhf(gv);
            int idx = b * H_DIM + hc;
            float c = fv * g_c[idx] + iv * gv;
            g_c[idx] = c;
            hout[idx] = ov * tanhf(c);
        }
    }
}

// ---------------------------------------------------------------------------
// MLP layer 1: z1 = tanh(h_final @ w1^T + b1), two heads. M=1024, N=513, K=512.
// 64x64 tile, thread 4x4 microtile.
// ---------------------------------------------------------------------------
__global__ __launch_bounds__(256) void mlp1_kernel(
    const float* __restrict__ lw1, const float* __restrict__ lb1,
    const float* __restrict__ vw1, const float* __restrict__ vb1)
{
    __shared__ float sA[KC * SIS];       // [k][b]  64
    __shared__ float sW[KC * SIS];       // [k][n]  64 (same stride works)

    const int head = blockIdx.z;
    const float* __restrict__ w  = head ? vw1 : lw1;
    const float* __restrict__ b1 = head ? vb1 : lb1;
    const float* __restrict__ A  = g_h[0];        // s=199 wrote buffer 0
    float* __restrict__ z1 = g_z1[head];

    const int n0 = blockIdx.x * 64;
    const int b0 = blockIdx.y * 64;
    const int tid = threadIdx.x;
    const int tx = tid & 15, ty = tid >> 4;

    float acc[4][4];
#pragma unroll
    for (int i = 0; i < 4; i++)
#pragma unroll
        for (int j = 0; j < 4; j++) acc[i][j] = 0.0f;

    for (int k0 = 0; k0 < H_DIM; k0 += KC) {
#pragma unroll
        for (int i = 0; i < 8; i++) {
            int lin = tid + i * 256;
            int kk = lin & 31, bb = lin >> 5;
            sA[kk * SIS + bb] = A[(b0 + bb) * H_DIM + k0 + kk];
        }
#pragma unroll
        for (int i = 0; i < 8; i++) {
            int lin = tid + i * 256;
            int kk = lin & 31, nn = lin >> 5;
            int n = n0 + nn;
            sW[kk * SIS + nn] = (n < H1) ? w[n * H_DIM + k0 + kk] : 0.0f;
        }
        __syncthreads();
#pragma unroll
        for (int k = 0; k < KC; k++) {
            float rA[4], rW[4];
#pragma unroll
            for (int i = 0; i < 4; i++) rA[i] = sA[k * SIS + ty + 16 * i];
#pragma unroll
            for (int j = 0; j < 4; j++) rW[j] = sW[k * SIS + tx + 16 * j];
#pragma unroll
            for (int i = 0; i < 4; i++)
#pragma unroll
                for (int j = 0; j < 4; j++)
                    acc[i][j] += rA[i] * rW[j];
        }
        __syncthreads();
    }

#pragma unroll
    for (int j = 0; j < 4; j++) {
        int n = n0 + tx + 16 * j;
        if (n < H1) {
            float bv = b1[n];
#pragma unroll
            for (int i = 0; i < 4; i++) {
                int b = b0 + ty + 16 * i;
                z1[b * H1 + n] = tanhf(acc[i][j] + bv);
            }
        }
    }
}

// ---------------------------------------------------------------------------
// MLP layer 2: out = tanh(z1 @ w2^T + b2), two heads. M=1024, N=32, K=513.
// Block: 32 batch rows; thread = (o, row-group), smem-staged operands.
// ---------------------------------------------------------------------------
__global__ __launch_bounds__(256) void mlp2_kernel(
    const float* __restrict__ lw2, const float* __restrict__ lb2,
    const float* __restrict__ vw2, const float* __restrict__ vb2,
    float* __restrict__ out)
{
    __shared__ float z1s[32 * 65];  // [row][kk]
    __shared__ float w2s[32 * 65];  // [o][kk]

    const int head = blockIdx.y;
    const float* __restrict__ w2 = head ? vw2 : lw2;
    const float* __restrict__ b2 = head ? vb2 : lb2;
    const float* __restrict__ z1 = g_z1[head];

    const int r0 = blockIdx.x * 32;
    const int tid = threadIdx.x;
    const int o  = tid & 31;
    const int rg = tid >> 5;        // 0..7 -> rows rg*4 .. rg*4+3

    float acc[4] = {0.f, 0.f, 0.f, 0.f};

    for (int k0 = 0; k0 < H1; k0 += 64) {
#pragma unroll
        for (int i = 0; i < 8; i++) {
            int lin = tid + i * 256;
            int kk = lin & 63, rr = lin >> 6;
            int k = k0 + kk;
            z1s[rr * 65 + kk] = (k < H1) ? z1[(r0 + rr) * H1 + k] : 0.0f;
            w2s[rr * 65 + kk] = (k < H1) ? w2[rr * H1 + k] : 0.0f;   // rr == o row
        }
        __syncthreads();
#pragma unroll
        for (int kk = 0; kk < 64; kk++) {
            float wv = w2s[o * 65 + kk];
#pragma unroll
            for (int r = 0; r < 4; r++)
                acc[r] += z1s[(rg * 4 + r) * 65 + kk] * wv;
        }
        __syncthreads();
    }

    float bv = b2[o];
#pragma unroll
    for (int r = 0; r < 4; r++) {
        int b = r0 + rg * 4 + r;
        out[(size_t)head * BATCH * OUT_DIM + b * OUT_DIM + o] = tanhf(acc[r] + bv);
    }
}

// ---------------------------------------------------------------------------
// Launch
// ---------------------------------------------------------------------------
extern "C" void kernel_launch(void* const* d_in, const int* in_sizes, int n_in,
                              void* d_out, int out_size) {
    const float* x    = (const float*)d_in[0];
    const float* a    = (const float*)d_in[1];
    const float* m    = (const float*)d_in[2];
    const float* w_ih = (const float*)d_in[3];
    const float* w_hh = (const float*)d_in[4];
    const float* b_ih = (const float*)d_in[5];
    const float* b_hh = (const float*)d_in[6];
    const float* lw1  = (const float*)d_in[7];
    const float* lb1  = (const float*)d_in[8];
    const float* lw2  = (const float*)d_in[9];
    const float* lb2  = (const float*)d_in[10];
    const float* vw1  = (const float*)d_in[11];
    const float* vb1  = (const float*)d_in[12];
    const float* vw2  = (const float*)d_in[13];
    const float* vb2  = (const float*)d_in[14];

    zero_kernel<<<512, 256>>>();
    maxm_kernel<<<1, 256>>>(m);

    for (int s = 0; s < T_STEPS; s++)
        step_kernel<<<dim3(16, 16), 256>>>(x, a, w_ih, w_hh, b_ih, b_hh, s);

    mlp1_kernel<<<dim3(9, 16, 2), 256>>>(lw1, lb1, vw1, vb1);
    mlp2_kernel<<<dim3(32, 2), 256>>>(lw2, lb2, vw2, vb2, (float*)d_out);
}